// round 7
// baseline (speedup 1.0000x reference)
#include <cuda_runtime.h>
#include <math.h>
#include <stdint.h>

#define NN      32768
#define NHOPS   6
#define NFEAT_  512
#define NSSF_   256
#define NCLASS_ 40
#define NEG_    0.2f
#define COS_EPS_ 1e-6f

// output layout (flattened tuple, element offsets)
#define OUT_OFF   0
#define SSFN_OFF  (NN*NCLASS_)                    // 1310720
#define Z_OFF     (SSFN_OFF + NSSF_*NCLASS_)      // 1320960
#define LOSS_OFF  (Z_OFF + NN*NSSF_)              // 9709568
#define SIGMA_OFF (LOSS_OFF + NN*NCLASS_)         // 11020288

// scratch (static device globals — no runtime allocation)
__device__ float g_z1[(long)NN * 512];
__device__ float g_zsq[NN];
__device__ float g_zn[NN];
__device__ float g_csq[NCLASS_];
__device__ float g_cn[NCLASS_];

// ---------------------------------------------------------------------------
// helpers
// ---------------------------------------------------------------------------
__device__ __forceinline__ uint32_t f2tf(float x) {
    uint32_t y;
    asm("cvt.rna.tf32.f32 %0, %1;" : "=r"(y) : "f"(x));
    return y;
}
__device__ __forceinline__ void mma8(float c[4], const uint32_t a[4],
                                     const uint32_t b[2]) {
    asm volatile(
        "mma.sync.aligned.m16n8k8.row.col.f32.tf32.tf32.f32 "
        "{%0,%1,%2,%3}, {%4,%5,%6,%7}, {%8,%9}, {%0,%1,%2,%3};\n"
        : "+f"(c[0]), "+f"(c[1]), "+f"(c[2]), "+f"(c[3])
        : "r"(a[0]), "r"(a[1]), "r"(a[2]), "r"(a[3]), "r"(b[0]), "r"(b[1]));
}

// ---------------------------------------------------------------------------
// K0: exact sparsify threshold (5121-st smallest of |ssf|), ssf_norm,
// per-class column norms, sigma copy. One block.
// ---------------------------------------------------------------------------
__global__ void __launch_bounds__(256) smn_k0_ssf(
    const float* __restrict__ ssf, const float* __restrict__ sigma,
    float* __restrict__ dout)
{
    __shared__ float fbuf[NSSF_ * NCLASS_];
    __shared__ int   cnt_s[256];
    unsigned* keys = reinterpret_cast<unsigned*>(fbuf);
    const int tid = threadIdx.x;

    for (int i = tid; i < NSSF_ * NCLASS_; i += 256)
        keys[i] = __float_as_uint(fabsf(ssf[i]));
    __syncthreads();

    unsigned lo = 0u, hi = 0x7f800000u;
    while (lo < hi) {
        unsigned mid = (lo + hi) >> 1;
        int c = 0;
        for (int i = tid; i < NSSF_ * NCLASS_; i += 256) c += (keys[i] <= mid);
        cnt_s[tid] = c;
        __syncthreads();
        for (int s = 128; s > 0; s >>= 1) {
            if (tid < s) cnt_s[tid] += cnt_s[tid + s];
            __syncthreads();
        }
        int total = cnt_s[0];
        __syncthreads();
        if (total >= 5121) hi = mid; else lo = mid + 1;
    }
    const float thr = __uint_as_float(lo);

    float row[NCLASS_];
    float rs = 0.f;
    const float* srow = ssf + tid * NCLASS_;
#pragma unroll
    for (int j = 0; j < NCLASS_; j++) {
        float v = srow[j];
        v = (fabsf(v) >= thr) ? v : 0.f;
        row[j] = v;
        rs += fabsf(v);
    }
    const float inv = 1.f / fmaxf(rs, 1e-12f);
#pragma unroll
    for (int j = 0; j < NCLASS_; j++) {
        float v = row[j] * inv;
        dout[SSFN_OFF + tid * NCLASS_ + j] = v;
        fbuf[tid * NCLASS_ + j] = v;
    }
    __syncthreads();

    if (tid < NCLASS_) {
        float c2 = 0.f;
        for (int i = 0; i < NSSF_; i++) {
            float v = fbuf[i * NCLASS_ + tid];
            c2 += v * v;
        }
        g_csq[tid] = c2;
        g_cn[tid]  = fmaxf(sqrtf(c2), COS_EPS_);
    }
    if (tid < 2) dout[SIGMA_OFF + tid] = sigma[tid];
}

// ---------------------------------------------------------------------------
// K1 (tf32 mma, double-buffered): h = lrelu(x @ W_pre^T + b) -> hop softmax.
// Block: 192 rows (32 nodes) x 128 cols (2 heads). 8 warps as 4(M)x2(N),
// warp tile 48x64 — halves A fragment duplication vs the 96-row variant.
// Dynamic smem: atts[768] | As[2][192][36] u32 | Bs[2][128][36] u32 = 95232 B.
// ---------------------------------------------------------------------------
__global__ void __launch_bounds__(256) smn_k1_tc(
    const float* __restrict__ x, const float* __restrict__ Wp,
    const float* __restrict__ bp, const float* __restrict__ att)
{
    extern __shared__ uint32_t dynsmem[];
    float*    atts = (float*)dynsmem;         // 768
    uint32_t* As   = dynsmem + 768;           // 2 * 192*36
    uint32_t* Bs   = As + 2 * 192 * 36;       // 2 * 128*36

    const int tid  = threadIdx.x;
    const int lane = tid & 31, warp = tid >> 5;
    const int warpM = warp >> 1, warpN = warp & 1;
    const int g = lane >> 2, t = lane & 3;
    const int node0 = blockIdx.y * 32;
    const int col0  = blockIdx.x * 128;
    const long row0 = (long)node0 * NHOPS;

    for (int i = tid; i < 768; i += 256)
        atts[i] = att[2 * blockIdx.x * 384 + i];

    const int ar[6] = { (tid) >> 3,         (tid + 256) >> 3,
                        (tid + 512) >> 3,   (tid + 768) >> 3,
                        (tid + 1024) >> 3,  (tid + 1280) >> 3 };
    const int ac = (tid & 7) * 4;
    float4 a_reg[6], b_reg[4];

    float acc[3][8][4];
#pragma unroll
    for (int mf = 0; mf < 3; mf++)
#pragma unroll
        for (int nf = 0; nf < 8; nf++)
#pragma unroll
            for (int v = 0; v < 4; v++) acc[mf][nf][v] = 0.f;

    // prologue: load + stage chunk 0
#pragma unroll
    for (int i = 0; i < 6; i++)
        a_reg[i] = *(const float4*)(x + (row0 + ar[i]) * NFEAT_ + ac);
#pragma unroll
    for (int i = 0; i < 4; i++) {
        int n = (tid + i * 256) >> 3;
        b_reg[i] = *(const float4*)(Wp + (long)(col0 + n) * NFEAT_ + ac);
    }
#pragma unroll
    for (int i = 0; i < 6; i++) {
        uint32_t* d = As + ar[i] * 36 + ac;
        d[0] = f2tf(a_reg[i].x); d[1] = f2tf(a_reg[i].y);
        d[2] = f2tf(a_reg[i].z); d[3] = f2tf(a_reg[i].w);
    }
#pragma unroll
    for (int i = 0; i < 4; i++) {
        int n = (tid + i * 256) >> 3;
        uint32_t* d = Bs + n * 36 + ac;
        d[0] = f2tf(b_reg[i].x); d[1] = f2tf(b_reg[i].y);
        d[2] = f2tf(b_reg[i].z); d[3] = f2tf(b_reg[i].w);
    }
    __syncthreads();

    for (int it = 0; it < 16; it++) {
        const int buf = it & 1;
        if (it < 15) {
            const int ks = (it + 1) * 32;
#pragma unroll
            for (int i = 0; i < 6; i++)
                a_reg[i] = *(const float4*)(x + (row0 + ar[i]) * NFEAT_ + ks + ac);
#pragma unroll
            for (int i = 0; i < 4; i++) {
                int n = (tid + i * 256) >> 3;
                b_reg[i] = *(const float4*)(Wp + (long)(col0 + n) * NFEAT_ + ks + ac);
            }
        }
        const uint32_t* Ab = As + buf * 6912;
        const uint32_t* Bb = Bs + buf * 4608;
#pragma unroll
        for (int kk = 0; kk < 4; kk++) {
            const int k8 = kk * 8;
            uint32_t af[3][4], bf[8][2];
#pragma unroll
            for (int mf = 0; mf < 3; mf++) {
                const int rb = warpM * 48 + mf * 16;
                af[mf][0] = Ab[(rb + g)     * 36 + k8 + t];
                af[mf][1] = Ab[(rb + g + 8) * 36 + k8 + t];
                af[mf][2] = Ab[(rb + g)     * 36 + k8 + t + 4];
                af[mf][3] = Ab[(rb + g + 8) * 36 + k8 + t + 4];
            }
#pragma unroll
            for (int nf = 0; nf < 8; nf++) {
                const int nb = warpN * 64 + nf * 8;
                bf[nf][0] = Bb[(nb + g) * 36 + k8 + t];
                bf[nf][1] = Bb[(nb + g) * 36 + k8 + t + 4];
            }
#pragma unroll
            for (int mf = 0; mf < 3; mf++)
#pragma unroll
                for (int nf = 0; nf < 8; nf++)
                    mma8(acc[mf][nf], af[mf], bf[nf]);
        }
        if (it < 15) {
            uint32_t* An = As + (buf ^ 1) * 6912;
            uint32_t* Bn = Bs + (buf ^ 1) * 4608;
#pragma unroll
            for (int i = 0; i < 6; i++) {
                uint32_t* d = An + ar[i] * 36 + ac;
                d[0] = f2tf(a_reg[i].x); d[1] = f2tf(a_reg[i].y);
                d[2] = f2tf(a_reg[i].z); d[3] = f2tf(a_reg[i].w);
            }
#pragma unroll
            for (int i = 0; i < 4; i++) {
                int n = (tid + i * 256) >> 3;
                uint32_t* d = Bn + n * 36 + ac;
                d[0] = f2tf(b_reg[i].x); d[1] = f2tf(b_reg[i].y);
                d[2] = f2tf(b_reg[i].z); d[3] = f2tf(b_reg[i].w);
            }
        }
        __syncthreads();
    }

    // epilogue: two 64-col halves through smem (Cs [192][68] reuses As region)
    float* Cs = (float*)As;
#pragma unroll
    for (int half = 0; half < 2; half++) {
        if (warpN == half) {
#pragma unroll
            for (int mf = 0; mf < 3; mf++)
#pragma unroll
                for (int nf = 0; nf < 8; nf++) {
                    const int r  = warpM * 48 + mf * 16 + g;
                    const int cc = nf * 8 + t * 2;
                    Cs[r * 68 + cc]           = acc[mf][nf][0];
                    Cs[r * 68 + cc + 1]       = acc[mf][nf][1];
                    Cs[(r + 8) * 68 + cc]     = acc[mf][nf][2];
                    Cs[(r + 8) * 68 + cc + 1] = acc[mf][nf][3];
                }
        }
        __syncthreads();
        {
            const int ty = tid >> 4, tx = tid & 15;
            const int cg = half * 64 + tx * 4;
            float4 b4 = *(const float4*)(bp + col0 + cg);
            float bv[4] = {b4.x, b4.y, b4.z, b4.w};
#pragma unroll
            for (int np = 0; np < 2; np++) {
                const int lnode = np * 16 + ty;
                const int node  = node0 + lnode;
                float zr[4];
#pragma unroll
                for (int c = 0; c < 4; c++) {
                    float h[NHOPS], am[NHOPS], s[NHOPS];
#pragma unroll
                    for (int r = 0; r < NHOPS; r++) {
                        float v = Cs[(lnode * 6 + r) * 68 + tx * 4 + c] + bv[c];
                        v = v > 0.f ? v : NEG_ * v;
                        h[r]  = v;
                        am[r] = v * atts[half * 384 + r * 64 + tx * 4 + c];
                    }
                    float m = -1e30f;
#pragma unroll
                    for (int r = 0; r < NHOPS; r++) {
                        float u = am[0] + am[r];
                        u = u > 0.f ? u : NEG_ * u;
                        s[r] = u;
                        m = fmaxf(m, u);
                    }
                    float den = 0.f, num = 0.f;
#pragma unroll
                    for (int r = 0; r < NHOPS; r++) {
                        float w = expf(s[r] - m);
                        den += w;
                        num += h[r] * w;
                    }
                    zr[c] = num / den;
                }
                *(float4*)&g_z1[(long)node * 512 + col0 + cg] =
                    make_float4(zr[0], zr[1], zr[2], zr[3]);
            }
        }
        __syncthreads();
    }
}

// ---------------------------------------------------------------------------
// K2 (tf32 mma, double-buffered, round-4 layout): z = lrelu(z1 @ W_post^T+b),
// plus per-row sum-of-squares + norm. Block 128x256, 512 threads,
// warp tile 32x64. Dynamic smem: As[2][128][36] | Bs[2][256][36] = 110592 B.
// ---------------------------------------------------------------------------
__global__ void __launch_bounds__(512) smn_k2_tc(
    const float* __restrict__ Wq, const float* __restrict__ bq,
    float* __restrict__ dout)
{
    extern __shared__ uint32_t dynsmem[];
    uint32_t* As = dynsmem;                   // 2 * 128*36
    uint32_t* Bs = As + 2 * 128 * 36;         // 2 * 256*36
    __shared__ float bias_s[256];

    const int tid  = threadIdx.x;
    const int lane = tid & 31, warp = tid >> 5;
    const int warpM = warp >> 2, warpN = warp & 3;
    const int g = lane >> 2, t = lane & 3;
    const long row0 = (long)blockIdx.x * 128;

    if (tid < 256) bias_s[tid] = bq[tid];

    const int ar[2] = { (tid + 0) >> 3, (tid + 512) >> 3 };
    const int ac    = (tid & 7) * 4;
    float4 a_reg[2], b_reg[4];

    float acc[2][8][4];
#pragma unroll
    for (int mf = 0; mf < 2; mf++)
#pragma unroll
        for (int nf = 0; nf < 8; nf++)
#pragma unroll
            for (int v = 0; v < 4; v++) acc[mf][nf][v] = 0.f;

#pragma unroll
    for (int i = 0; i < 2; i++)
        a_reg[i] = *(const float4*)(g_z1 + (row0 + ar[i]) * 512 + ac);
#pragma unroll
    for (int i = 0; i < 4; i++) {
        int n = (tid + i * 512) >> 3;
        b_reg[i] = *(const float4*)(Wq + (long)n * 512 + ac);
    }
#pragma unroll
    for (int i = 0; i < 2; i++) {
        uint32_t* d = As + ar[i] * 36 + ac;
        d[0] = f2tf(a_reg[i].x); d[1] = f2tf(a_reg[i].y);
        d[2] = f2tf(a_reg[i].z); d[3] = f2tf(a_reg[i].w);
    }
#pragma unroll
    for (int i = 0; i < 4; i++) {
        int n = (tid + i * 512) >> 3;
        uint32_t* d = Bs + n * 36 + ac;
        d[0] = f2tf(b_reg[i].x); d[1] = f2tf(b_reg[i].y);
        d[2] = f2tf(b_reg[i].z); d[3] = f2tf(b_reg[i].w);
    }
    __syncthreads();

    for (int it = 0; it < 16; it++) {
        const int buf = it & 1;
        if (it < 15) {
            const int ks = (it + 1) * 32;
#pragma unroll
            for (int i = 0; i < 2; i++)
                a_reg[i] = *(const float4*)(g_z1 + (row0 + ar[i]) * 512 + ks + ac);
#pragma unroll
            for (int i = 0; i < 4; i++) {
                int n = (tid + i * 512) >> 3;
                b_reg[i] = *(const float4*)(Wq + (long)n * 512 + ks + ac);
            }
        }
        const uint32_t* Ab = As + buf * 4608;
        const uint32_t* Bb = Bs + buf * 9216;
#pragma unroll
        for (int kk = 0; kk < 4; kk++) {
            const int k8 = kk * 8;
            uint32_t af[2][4], bf[8][2];
#pragma unroll
            for (int mf = 0; mf < 2; mf++) {
                const int rb = warpM * 32 + mf * 16;
                af[mf][0] = Ab[(rb + g)     * 36 + k8 + t];
                af[mf][1] = Ab[(rb + g + 8) * 36 + k8 + t];
                af[mf][2] = Ab[(rb + g)     * 36 + k8 + t + 4];
                af[mf][3] = Ab[(rb + g + 8) * 36 + k8 + t + 4];
            }
#pragma unroll
            for (int nf = 0; nf < 8; nf++) {
                const int nb = warpN * 64 + nf * 8;
                bf[nf][0] = Bb[(nb + g) * 36 + k8 + t];
                bf[nf][1] = Bb[(nb + g) * 36 + k8 + t + 4];
            }
#pragma unroll
            for (int mf = 0; mf < 2; mf++)
#pragma unroll
                for (int nf = 0; nf < 8; nf++)
                    mma8(acc[mf][nf], af[mf], bf[nf]);
        }
        if (it < 15) {
            uint32_t* An = As + (buf ^ 1) * 4608;
            uint32_t* Bn = Bs + (buf ^ 1) * 9216;
#pragma unroll
            for (int i = 0; i < 2; i++) {
                uint32_t* d = An + ar[i] * 36 + ac;
                d[0] = f2tf(a_reg[i].x); d[1] = f2tf(a_reg[i].y);
                d[2] = f2tf(a_reg[i].z); d[3] = f2tf(a_reg[i].w);
            }
#pragma unroll
            for (int i = 0; i < 4; i++) {
                int n = (tid + i * 512) >> 3;
                uint32_t* d = Bn + n * 36 + ac;
                d[0] = f2tf(b_reg[i].x); d[1] = f2tf(b_reg[i].y);
                d[2] = f2tf(b_reg[i].z); d[3] = f2tf(b_reg[i].w);
            }
        }
        __syncthreads();
    }

    // epilogue: bias + lrelu + store z + per-row sum of squares
    float* part = (float*)As;     // [128][4]
    float zp[4] = {0.f, 0.f, 0.f, 0.f};
#pragma unroll
    for (int mf = 0; mf < 2; mf++) {
#pragma unroll
        for (int nf = 0; nf < 8; nf++) {
            const int rl  = warpM * 32 + mf * 16 + g;
            const int col = warpN * 64 + nf * 8 + t * 2;
            float v0 = acc[mf][nf][0] + bias_s[col];
            float v1 = acc[mf][nf][1] + bias_s[col + 1];
            float v2 = acc[mf][nf][2] + bias_s[col];
            float v3 = acc[mf][nf][3] + bias_s[col + 1];
            v0 = v0 > 0.f ? v0 : NEG_ * v0;
            v1 = v1 > 0.f ? v1 : NEG_ * v1;
            v2 = v2 > 0.f ? v2 : NEG_ * v2;
            v3 = v3 > 0.f ? v3 : NEG_ * v3;
            *(float2*)&dout[Z_OFF + (row0 + rl) * 256 + col] =
                make_float2(v0, v1);
            *(float2*)&dout[Z_OFF + (row0 + rl + 8) * 256 + col] =
                make_float2(v2, v3);
            zp[mf * 2]     += v0 * v0 + v1 * v1;
            zp[mf * 2 + 1] += v2 * v2 + v3 * v3;
        }
    }
#pragma unroll
    for (int j = 0; j < 4; j++) {
        zp[j] += __shfl_xor_sync(0xffffffffu, zp[j], 1);
        zp[j] += __shfl_xor_sync(0xffffffffu, zp[j], 2);
    }
    __syncthreads();
    if (t == 0) {
#pragma unroll
        for (int j = 0; j < 4; j++) {
            const int rl = warpM * 32 + (j >> 1) * 16 + g + (j & 1) * 8;
            part[rl * 4 + warpN] = zp[j];
        }
    }
    __syncthreads();
    if (tid < 128) {
        float s = part[tid * 4] + part[tid * 4 + 1]
                + part[tid * 4 + 2] + part[tid * 4 + 3];
        g_zsq[row0 + tid] = s;
        g_zn[row0 + tid]  = fmaxf(sqrtf(s), COS_EPS_);
    }
}

// ---------------------------------------------------------------------------
// K3 (tf32 mma, measured 24.4us): out = z @ ssfn; dist/sim; log-softmaxes.
// dynsmem u32: Bs 10240 | As 2*4096  (=73728 B)
// ---------------------------------------------------------------------------
__global__ void __launch_bounds__(256) smn_k3_tc(float* __restrict__ dout)
{
    extern __shared__ uint32_t dynsmem[];
    uint32_t* Bs = dynsmem;            // 5 n8grp * 32 kk * 64
    uint32_t* As = dynsmem + 10240;    // 2 * 8 tiles * 4 kk * 128
    __shared__ float csq_s[NCLASS_], cn_s[NCLASS_];

    const int tid  = threadIdx.x;
    const int lane = tid & 31, warp = tid >> 5;
    const int g = lane >> 2, t = lane & 3;
    const long row0 = (long)blockIdx.x * 128;
    const float* zg = dout + Z_OFF;

    for (int e = tid; e < NSSF_ * NCLASS_; e += 256) {
        int k = e / NCLASS_, n = e - k * NCLASS_;
        float v = dout[SSFN_OFF + e];
        int kk = k >> 3, kp = k & 7, tt = kp & 3, hi2 = kp >> 2;
        int phys = (((n & 7) * 4 + tt) + kk * 2) & 31;
        Bs[((n >> 3) * 32 + kk) * 64 + phys * 2 + hi2] = f2tf(v);
    }
    if (tid < NCLASS_) { csq_s[tid] = g_csq[tid]; cn_s[tid] = g_cn[tid]; }

    const int ar[4] = { (tid) >> 3, (tid + 256) >> 3,
                        (tid + 512) >> 3, (tid + 768) >> 3 };
    const int ac  = (tid & 7) * 4;
    const int kkt = ac >> 3, hit = (ac >> 2) & 1, rot = kkt * 2;
    float4 a_reg[4];

    auto stageA3 = [&](uint32_t* dstbuf) {
#pragma unroll
        for (int i = 0; i < 4; i++) {
            const int r = ar[i];
            uint32_t* d = dstbuf + (((r >> 4) * 4 + kkt) * 128)
                        + ((r >> 3) & 1) + 2 * hit;
            const int l0 = (r & 7) * 4;
            d[(((l0 + 0) + rot) & 31) * 4] = f2tf(a_reg[i].x);
            d[(((l0 + 1) + rot) & 31) * 4] = f2tf(a_reg[i].y);
            d[(((l0 + 2) + rot) & 31) * 4] = f2tf(a_reg[i].z);
            d[(((l0 + 3) + rot) & 31) * 4] = f2tf(a_reg[i].w);
        }
    };

    float acc[5][4];
#pragma unroll
    for (int nf = 0; nf < 5; nf++)
#pragma unroll
        for (int v = 0; v < 4; v++) acc[nf][v] = 0.f;

#pragma unroll
    for (int i = 0; i < 4; i++)
        a_reg[i] = *(const float4*)(zg + (row0 + ar[i]) * 256 + ac);
    stageA3(As);
    __syncthreads();

    for (int it = 0; it < 8; it++) {
        const int buf = it & 1;
        if (it < 7) {
            const int ks = (it + 1) * 32;
#pragma unroll
            for (int i = 0; i < 4; i++)
                a_reg[i] = *(const float4*)(zg + (row0 + ar[i]) * 256 + ks + ac);
        }
        const uint32_t* Ab = As + buf * 4096;
#pragma unroll
        for (int kk = 0; kk < 4; kk++) {
            const int kkg = it * 4 + kk;
            const int prA = (lane + kk * 2) & 31;
            const int prB = (lane + kkg * 2) & 31;
            uint4 av = *(const uint4*)&Ab[(warp * 4 + kk) * 128 + prA * 4];
#pragma unroll
            for (int nf = 0; nf < 5; nf++) {
                uint2 bv = *(const uint2*)&Bs[(nf * 32 + kkg) * 64 + prB * 2];
                mma8(acc[nf], reinterpret_cast<const uint32_t*>(&av),
                     reinterpret_cast<const uint32_t*>(&bv));
            }
        }
        if (it < 7) stageA3(As + (buf ^ 1) * 4096);
        __syncthreads();
    }

#pragma unroll
    for (int rs = 0; rs < 2; rs++) {
        const long row = row0 + warp * 16 + g + rs * 8;
        const float zsq = g_zsq[row];
        const float zn  = g_zn[row];
        float dv[5][2], sv[5][2], av[5][2];
        float md = -1e30f, ms = -1e30f;
#pragma unroll
        for (int nf = 0; nf < 5; nf++) {
#pragma unroll
            for (int u = 0; u < 2; u++) {
                const int col = nf * 8 + t * 2 + u;
                float a = acc[nf][rs * 2 + u];
                av[nf][u] = a;
                float d = -sqrtf(fmaxf(zsq + csq_s[col] - 2.f * a, 0.f));
                float s = a / (zn * cn_s[col]);
                dv[nf][u] = d; sv[nf][u] = s;
                md = fmaxf(md, d); ms = fmaxf(ms, s);
            }
        }
        md = fmaxf(md, __shfl_xor_sync(0xffffffffu, md, 1));
        md = fmaxf(md, __shfl_xor_sync(0xffffffffu, md, 2));
        ms = fmaxf(ms, __shfl_xor_sync(0xffffffffu, ms, 1));
        ms = fmaxf(ms, __shfl_xor_sync(0xffffffffu, ms, 2));
        float ed = 0.f, es = 0.f;
#pragma unroll
        for (int nf = 0; nf < 5; nf++)
#pragma unroll
            for (int u = 0; u < 2; u++) {
                ed += expf(dv[nf][u] - md);
                es += expf(sv[nf][u] - ms);
            }
        ed += __shfl_xor_sync(0xffffffffu, ed, 1);
        ed += __shfl_xor_sync(0xffffffffu, ed, 2);
        es += __shfl_xor_sync(0xffffffffu, es, 1);
        es += __shfl_xor_sync(0xffffffffu, es, 2);
        const float lse_d = md + logf(ed);
        const float lse_s = ms + logf(es);
#pragma unroll
        for (int nf = 0; nf < 5; nf++) {
            const int col = nf * 8 + t * 2;
            *(float2*)&dout[OUT_OFF + row * NCLASS_ + col] =
                make_float2(av[nf][0], av[nf][1]);
            *(float2*)&dout[LOSS_OFF + row * NCLASS_ + col] = make_float2(
                0.5f * ((dv[nf][0] - lse_d) + (sv[nf][0] - lse_s)),
                0.5f * ((dv[nf][1] - lse_d) + (sv[nf][1] - lse_s)));
        }
    }
}

// ---------------------------------------------------------------------------
extern "C" void kernel_launch(void* const* d_in, const int* in_sizes, int n_in,
                              void* d_out, int out_size)
{
    const float* x      = (const float*)d_in[0];
    const float* W_pre  = (const float*)d_in[1];
    const float* b_pre  = (const float*)d_in[2];
    const float* att    = (const float*)d_in[3];
    const float* W_post = (const float*)d_in[4];
    const float* b_post = (const float*)d_in[5];
    const float* ssf    = (const float*)d_in[6];
    const float* sigma  = (const float*)d_in[7];
    float* dout = (float*)d_out;

    const int K1_SMEM = (768 + 2 * 192 * 36 + 2 * 128 * 36) * 4;  // 95232
    const int K2_SMEM = (2 * 128 * 36 + 2 * 256 * 36) * 4;        // 110592
    const int K3_SMEM = (10240 + 2 * 4096) * 4;                   // 73728
    cudaFuncSetAttribute(smn_k1_tc,
                         cudaFuncAttributeMaxDynamicSharedMemorySize, K1_SMEM);
    cudaFuncSetAttribute(smn_k2_tc,
                         cudaFuncAttributeMaxDynamicSharedMemorySize, K2_SMEM);
    cudaFuncSetAttribute(smn_k3_tc,
                         cudaFuncAttributeMaxDynamicSharedMemorySize, K3_SMEM);

    smn_k0_ssf<<<1, 256>>>(ssf, sigma, dout);
    smn_k1_tc<<<dim3(4, NN / 32), 256, K1_SMEM>>>(x, W_pre, b_pre, att);
    smn_k2_tc<<<NN / 128, 512, K2_SMEM>>>(W_post, b_post, dout);
    smn_k3_tc<<<NN / 128, 256, K3_SMEM>>>(dout);
}

// round 8
// speedup vs baseline: 1.0612x; 1.0612x over previous
#include <cuda_runtime.h>
#include <math.h>
#include <stdint.h>

#define NN      32768
#define NHOPS   6
#define NFEAT_  512
#define NSSF_   256
#define NCLASS_ 40
#define NEG_    0.2f
#define COS_EPS_ 1e-6f

// output layout (flattened tuple, element offsets)
#define OUT_OFF   0
#define SSFN_OFF  (NN*NCLASS_)                    // 1310720
#define Z_OFF     (SSFN_OFF + NSSF_*NCLASS_)      // 1320960
#define LOSS_OFF  (Z_OFF + NN*NSSF_)              // 9709568
#define SIGMA_OFF (LOSS_OFF + NN*NCLASS_)         // 11020288

// scratch (static device globals — no runtime allocation)
__device__ float g_z1[(long)NN * 512];
__device__ float g_zsq[NN];
__device__ float g_zn[NN];
__device__ float g_csq[NCLASS_];
__device__ float g_cn[NCLASS_];
__device__ uint32_t g_Wp_tf[512 * 512];   // W_pre pre-converted to tf32
__device__ uint32_t g_Wq_tf[256 * 512];   // W_post pre-converted to tf32

// ---------------------------------------------------------------------------
// helpers
// ---------------------------------------------------------------------------
__device__ __forceinline__ uint32_t f2tf(float x) {
    uint32_t y;
    asm("cvt.rna.tf32.f32 %0, %1;" : "=r"(y) : "f"(x));
    return y;
}
__device__ __forceinline__ void mma8(float c[4], const uint32_t a[4],
                                     const uint32_t b[2]) {
    asm volatile(
        "mma.sync.aligned.m16n8k8.row.col.f32.tf32.tf32.f32 "
        "{%0,%1,%2,%3}, {%4,%5,%6,%7}, {%8,%9}, {%0,%1,%2,%3};\n"
        : "+f"(c[0]), "+f"(c[1]), "+f"(c[2]), "+f"(c[3])
        : "r"(a[0]), "r"(a[1]), "r"(a[2]), "r"(a[3]), "r"(b[0]), "r"(b[1]));
}
__device__ __forceinline__ uint32_t smem_u32p(const void* p) {
    uint32_t a;
    asm("{ .reg .u64 t; cvta.to.shared.u64 t, %1; cvt.u32.u64 %0, t; }"
        : "=r"(a) : "l"(p));
    return a;
}
__device__ __forceinline__ void cp16(uint32_t saddr, const void* g) {
    asm volatile("cp.async.ca.shared.global [%0], [%1], 16;"
                 :: "r"(saddr), "l"(g));
}
#define CP_COMMIT() asm volatile("cp.async.commit_group;")
#define CP_WAIT0()  asm volatile("cp.async.wait_group 0;")

// ---------------------------------------------------------------------------
// Kw: pre-convert weights to tf32 (bit-identical to in-loop cvt.rna)
// ---------------------------------------------------------------------------
__global__ void __launch_bounds__(256) smn_wcvt(
    const float* __restrict__ Wp, const float* __restrict__ Wq)
{
    int i = blockIdx.x * 256 + threadIdx.x;
    if (i < 512 * 512) {
        g_Wp_tf[i] = f2tf(Wp[i]);
    } else {
        int j = i - 512 * 512;
        if (j < 256 * 512) g_Wq_tf[j] = f2tf(Wq[j]);
    }
}

// ---------------------------------------------------------------------------
// K0: exact sparsify threshold (5121-st smallest of |ssf|), ssf_norm,
// per-class column norms, sigma copy. One block.
// ---------------------------------------------------------------------------
__global__ void __launch_bounds__(256) smn_k0_ssf(
    const float* __restrict__ ssf, const float* __restrict__ sigma,
    float* __restrict__ dout)
{
    __shared__ float fbuf[NSSF_ * NCLASS_];
    __shared__ int   cnt_s[256];
    unsigned* keys = reinterpret_cast<unsigned*>(fbuf);
    const int tid = threadIdx.x;

    for (int i = tid; i < NSSF_ * NCLASS_; i += 256)
        keys[i] = __float_as_uint(fabsf(ssf[i]));
    __syncthreads();

    unsigned lo = 0u, hi = 0x7f800000u;
    while (lo < hi) {
        unsigned mid = (lo + hi) >> 1;
        int c = 0;
        for (int i = tid; i < NSSF_ * NCLASS_; i += 256) c += (keys[i] <= mid);
        cnt_s[tid] = c;
        __syncthreads();
        for (int s = 128; s > 0; s >>= 1) {
            if (tid < s) cnt_s[tid] += cnt_s[tid + s];
            __syncthreads();
        }
        int total = cnt_s[0];
        __syncthreads();
        if (total >= 5121) hi = mid; else lo = mid + 1;
    }
    const float thr = __uint_as_float(lo);

    float row[NCLASS_];
    float rs = 0.f;
    const float* srow = ssf + tid * NCLASS_;
#pragma unroll
    for (int j = 0; j < NCLASS_; j++) {
        float v = srow[j];
        v = (fabsf(v) >= thr) ? v : 0.f;
        row[j] = v;
        rs += fabsf(v);
    }
    const float inv = 1.f / fmaxf(rs, 1e-12f);
#pragma unroll
    for (int j = 0; j < NCLASS_; j++) {
        float v = row[j] * inv;
        dout[SSFN_OFF + tid * NCLASS_ + j] = v;
        fbuf[tid * NCLASS_ + j] = v;
    }
    __syncthreads();

    if (tid < NCLASS_) {
        float c2 = 0.f;
        for (int i = 0; i < NSSF_; i++) {
            float v = fbuf[i * NCLASS_ + tid];
            c2 += v * v;
        }
        g_csq[tid] = c2;
        g_cn[tid]  = fmaxf(sqrtf(c2), COS_EPS_);
    }
    if (tid < 2) dout[SIGMA_OFF + tid] = sigma[tid];
}

// ---------------------------------------------------------------------------
// K1 (tf32 mma, round-6 tiling + cp.async B): h = lrelu(x @ W_pre^T + b)
// -> hop softmax. Block 96x128, warp tile 48x32, register prefetch for A,
// cp.async for pre-converted B. Dynamic smem: atts[768] | As[2][96][36] |
// Bs[2][128][36] = 67584 B.
// ---------------------------------------------------------------------------
__global__ void __launch_bounds__(256) smn_k1_tc(
    const float* __restrict__ x,
    const float* __restrict__ bp, const float* __restrict__ att)
{
    extern __shared__ uint32_t dynsmem[];
    float*    atts = (float*)dynsmem;         // 768
    uint32_t* As   = dynsmem + 768;           // 2 * 96*36
    uint32_t* Bs   = As + 2 * 96 * 36;        // 2 * 128*36

    const int tid  = threadIdx.x;
    const int lane = tid & 31, warp = tid >> 5;
    const int warpM = warp >> 2, warpN = warp & 3;
    const int g = lane >> 2, t = lane & 3;
    const int node0 = blockIdx.y * 16;
    const int col0  = blockIdx.x * 128;
    const long row0 = (long)node0 * NHOPS;

    for (int i = tid; i < 768; i += 256)
        atts[i] = att[2 * blockIdx.x * 384 + i];

    const int ar[3] = { (tid + 0)   >> 3, (tid + 256) >> 3, (tid + 512) >> 3 };
    const int bn[4] = { (tid + 0)   >> 3, (tid + 256) >> 3,
                        (tid + 512) >> 3, (tid + 768) >> 3 };
    const int ac    = (tid & 7) * 4;
    float4 a_reg[3];

    // smem byte-addresses for this thread's 4 B slots (buffer 0)
    uint32_t bsa[4];
#pragma unroll
    for (int i = 0; i < 4; i++)
        bsa[i] = smem_u32p(&Bs[bn[i] * 36 + ac]);
    const uint32_t bufB_bytes = 4608 * 4;
    // global tf32 sources for B rows
    const uint32_t* wsrc[4];
#pragma unroll
    for (int i = 0; i < 4; i++)
        wsrc[i] = g_Wp_tf + (long)(col0 + bn[i]) * 512 + ac;

    float acc[3][4][4];
#pragma unroll
    for (int mf = 0; mf < 3; mf++)
#pragma unroll
        for (int nf = 0; nf < 4; nf++)
#pragma unroll
            for (int v = 0; v < 4; v++) acc[mf][nf][v] = 0.f;

    // prologue: B chunk0 via cp.async; A chunk0 via regs + cvt
#pragma unroll
    for (int i = 0; i < 4; i++) cp16(bsa[i], wsrc[i]);
    CP_COMMIT();
#pragma unroll
    for (int i = 0; i < 3; i++)
        a_reg[i] = *(const float4*)(x + (row0 + ar[i]) * NFEAT_ + ac);
#pragma unroll
    for (int i = 0; i < 3; i++) {
        uint32_t* d = As + ar[i] * 36 + ac;
        *(uint4*)d = make_uint4(f2tf(a_reg[i].x), f2tf(a_reg[i].y),
                                f2tf(a_reg[i].z), f2tf(a_reg[i].w));
    }
    CP_WAIT0();
    __syncthreads();

    for (int it = 0; it < 16; it++) {
        const int buf = it & 1;
        if (it < 15) {
            const int ks = (it + 1) * 32;
#pragma unroll
            for (int i = 0; i < 4; i++)
                cp16(bsa[i] + (buf ^ 1) * bufB_bytes, wsrc[i] + ks);
            CP_COMMIT();
#pragma unroll
            for (int i = 0; i < 3; i++)
                a_reg[i] = *(const float4*)(x + (row0 + ar[i]) * NFEAT_ + ks + ac);
        }
        const uint32_t* Ab = As + buf * 3456;
        const uint32_t* Bb = Bs + buf * 4608;
#pragma unroll
        for (int kk = 0; kk < 4; kk++) {
            const int k8 = kk * 8;
            uint32_t af[3][4], bf[4][2];
#pragma unroll
            for (int mf = 0; mf < 3; mf++) {
                const int rb = warpM * 48 + mf * 16;
                af[mf][0] = Ab[(rb + g)     * 36 + k8 + t];
                af[mf][1] = Ab[(rb + g + 8) * 36 + k8 + t];
                af[mf][2] = Ab[(rb + g)     * 36 + k8 + t + 4];
                af[mf][3] = Ab[(rb + g + 8) * 36 + k8 + t + 4];
            }
#pragma unroll
            for (int nf = 0; nf < 4; nf++) {
                const int nb = warpN * 32 + nf * 8;
                bf[nf][0] = Bb[(nb + g) * 36 + k8 + t];
                bf[nf][1] = Bb[(nb + g) * 36 + k8 + t + 4];
            }
#pragma unroll
            for (int mf = 0; mf < 3; mf++)
#pragma unroll
                for (int nf = 0; nf < 4; nf++)
                    mma8(acc[mf][nf], af[mf], bf[nf]);
        }
        if (it < 15) {
            uint32_t* An = As + (buf ^ 1) * 3456;
#pragma unroll
            for (int i = 0; i < 3; i++) {
                uint32_t* d = An + ar[i] * 36 + ac;
                *(uint4*)d = make_uint4(f2tf(a_reg[i].x), f2tf(a_reg[i].y),
                                        f2tf(a_reg[i].z), f2tf(a_reg[i].w));
            }
            CP_WAIT0();
        }
        __syncthreads();
    }

    // epilogue: two 64-col halves through smem (Cs [96][68] reuses As region)
    float* Cs = (float*)As;
#pragma unroll
    for (int half = 0; half < 2; half++) {
        if ((warpN >> 1) == half) {
#pragma unroll
            for (int mf = 0; mf < 3; mf++)
#pragma unroll
                for (int nf = 0; nf < 4; nf++) {
                    const int r  = warpM * 48 + mf * 16 + g;
                    const int cc = (warpN & 1) * 32 + nf * 8 + t * 2;
                    Cs[r * 68 + cc]           = acc[mf][nf][0];
                    Cs[r * 68 + cc + 1]       = acc[mf][nf][1];
                    Cs[(r + 8) * 68 + cc]     = acc[mf][nf][2];
                    Cs[(r + 8) * 68 + cc + 1] = acc[mf][nf][3];
                }
        }
        __syncthreads();
        {
            const int ty = tid >> 4, tx = tid & 15;
            const int node = node0 + ty;
            const int cg = half * 64 + tx * 4;
            float4 b4 = *(const float4*)(bp + col0 + cg);
            float bv[4] = {b4.x, b4.y, b4.z, b4.w};
            float zr[4];
#pragma unroll
            for (int c = 0; c < 4; c++) {
                float h[NHOPS], am[NHOPS], s[NHOPS];
#pragma unroll
                for (int r = 0; r < NHOPS; r++) {
                    float v = Cs[(ty * 6 + r) * 68 + tx * 4 + c] + bv[c];
                    v = v > 0.f ? v : NEG_ * v;
                    h[r]  = v;
                    am[r] = v * atts[half * 384 + r * 64 + tx * 4 + c];
                }
                float m = -1e30f;
#pragma unroll
                for (int r = 0; r < NHOPS; r++) {
                    float u = am[0] + am[r];
                    u = u > 0.f ? u : NEG_ * u;
                    s[r] = u;
                    m = fmaxf(m, u);
                }
                float den = 0.f, num = 0.f;
#pragma unroll
                for (int r = 0; r < NHOPS; r++) {
                    float w = expf(s[r] - m);
                    den += w;
                    num += h[r] * w;
                }
                zr[c] = num / den;
            }
            *(float4*)&g_z1[(long)node * 512 + col0 + cg] =
                make_float4(zr[0], zr[1], zr[2], zr[3]);
        }
        __syncthreads();
    }
}

// ---------------------------------------------------------------------------
// K2 (tf32 mma, round-4 tiling + cp.async B): z = lrelu(z1 @ W_post^T + b),
// plus per-row sum-of-squares + norm. Block 128x256, 512 threads,
// warp tile 32x64. Dynamic smem: As[2][128][36] | Bs[2][256][36] = 110592 B.
// ---------------------------------------------------------------------------
__global__ void __launch_bounds__(512) smn_k2_tc(
    const float* __restrict__ bq, float* __restrict__ dout)
{
    extern __shared__ uint32_t dynsmem[];
    uint32_t* As = dynsmem;                   // 2 * 128*36
    uint32_t* Bs = As + 2 * 128 * 36;         // 2 * 256*36
    __shared__ float bias_s[256];

    const int tid  = threadIdx.x;
    const int lane = tid & 31, warp = tid >> 5;
    const int warpM = warp >> 2, warpN = warp & 3;
    const int g = lane >> 2, t = lane & 3;
    const long row0 = (long)blockIdx.x * 128;

    if (tid < 256) bias_s[tid] = bq[tid];

    const int ar[2] = { (tid + 0) >> 3, (tid + 512) >> 3 };
    const int bn[4] = { (tid + 0) >> 3,    (tid + 512) >> 3,
                        (tid + 1024) >> 3, (tid + 1536) >> 3 };
    const int ac    = (tid & 7) * 4;
    float4 a_reg[2];

    uint32_t bsa[4];
#pragma unroll
    for (int i = 0; i < 4; i++)
        bsa[i] = smem_u32p(&Bs[bn[i] * 36 + ac]);
    const uint32_t bufB_bytes = 9216 * 4;
    const uint32_t* wsrc[4];
#pragma unroll
    for (int i = 0; i < 4; i++)
        wsrc[i] = g_Wq_tf + (long)bn[i] * 512 + ac;

    float acc[2][8][4];
#pragma unroll
    for (int mf = 0; mf < 2; mf++)
#pragma unroll
        for (int nf = 0; nf < 8; nf++)
#pragma unroll
            for (int v = 0; v < 4; v++) acc[mf][nf][v] = 0.f;

#pragma unroll
    for (int i = 0; i < 4; i++) cp16(bsa[i], wsrc[i]);
    CP_COMMIT();
#pragma unroll
    for (int i = 0; i < 2; i++)
        a_reg[i] = *(const float4*)(g_z1 + (row0 + ar[i]) * 512 + ac);
#pragma unroll
    for (int i = 0; i < 2; i++) {
        uint32_t* d = As + ar[i] * 36 + ac;
        *(uint4*)d = make_uint4(f2tf(a_reg[i].x), f2tf(a_reg[i].y),
                                f2tf(a_reg[i].z), f2tf(a_reg[i].w));
    }
    CP_WAIT0();
    __syncthreads();

    for (int it = 0; it < 16; it++) {
        const int buf = it & 1;
        if (it < 15) {
            const int ks = (it + 1) * 32;
#pragma unroll
            for (int i = 0; i < 4; i++)
                cp16(bsa[i] + (buf ^ 1) * bufB_bytes, wsrc[i] + ks);
            CP_COMMIT();
#pragma unroll
            for (int i = 0; i < 2; i++)
                a_reg[i] = *(const float4*)(g_z1 + (row0 + ar[i]) * 512 + ks + ac);
        }
        const uint32_t* Ab = As + buf * 4608;
        const uint32_t* Bb = Bs + buf * 9216;
#pragma unroll
        for (int kk = 0; kk < 4; kk++) {
            const int k8 = kk * 8;
            uint32_t af[2][4], bf[8][2];
#pragma unroll
            for (int mf = 0; mf < 2; mf++) {
                const int rb = warpM * 32 + mf * 16;
                af[mf][0] = Ab[(rb + g)     * 36 + k8 + t];
                af[mf][1] = Ab[(rb + g + 8) * 36 + k8 + t];
                af[mf][2] = Ab[(rb + g)     * 36 + k8 + t + 4];
                af[mf][3] = Ab[(rb + g + 8) * 36 + k8 + t + 4];
            }
#pragma unroll
            for (int nf = 0; nf < 8; nf++) {
                const int nb = warpN * 64 + nf * 8;
                bf[nf][0] = Bb[(nb + g) * 36 + k8 + t];
                bf[nf][1] = Bb[(nb + g) * 36 + k8 + t + 4];
            }
#pragma unroll
            for (int mf = 0; mf < 2; mf++)
#pragma unroll
                for (int nf = 0; nf < 8; nf++)
                    mma8(acc[mf][nf], af[mf], bf[nf]);
        }
        if (it < 15) {
            uint32_t* An = As + (buf ^ 1) * 4608;
#pragma unroll
            for (int i = 0; i < 2; i++) {
                uint32_t* d = An + ar[i] * 36 + ac;
                *(uint4*)d = make_uint4(f2tf(a_reg[i].x), f2tf(a_reg[i].y),
                                        f2tf(a_reg[i].z), f2tf(a_reg[i].w));
            }
            CP_WAIT0();
        }
        __syncthreads();
    }

    // epilogue: bias + lrelu + store z + per-row sum of squares
    float* part = (float*)As;     // [128][4]
    float zp[4] = {0.f, 0.f, 0.f, 0.f};
#pragma unroll
    for (int mf = 0; mf < 2; mf++) {
#pragma unroll
        for (int nf = 0; nf < 8; nf++) {
            const int rl  = warpM * 32 + mf * 16 + g;
            const int col = warpN * 64 + nf * 8 + t * 2;
            float v0 = acc[mf][nf][0] + bias_s[col];
            float v1 = acc[mf][nf][1] + bias_s[col + 1];
            float v2 = acc[mf][nf][2] + bias_s[col];
            float v3 = acc[mf][nf][3] + bias_s[col + 1];
            v0 = v0 > 0.f ? v0 : NEG_ * v0;
            v1 = v1 > 0.f ? v1 : NEG_ * v1;
            v2 = v2 > 0.f ? v2 : NEG_ * v2;
            v3 = v3 > 0.f ? v3 : NEG_ * v3;
            *(float2*)&dout[Z_OFF + (row0 + rl) * 256 + col] =
                make_float2(v0, v1);
            *(float2*)&dout[Z_OFF + (row0 + rl + 8) * 256 + col] =
                make_float2(v2, v3);
            zp[mf * 2]     += v0 * v0 + v1 * v1;
            zp[mf * 2 + 1] += v2 * v2 + v3 * v3;
        }
    }
#pragma unroll
    for (int j = 0; j < 4; j++) {
        zp[j] += __shfl_xor_sync(0xffffffffu, zp[j], 1);
        zp[j] += __shfl_xor_sync(0xffffffffu, zp[j], 2);
    }
    __syncthreads();
    if (t == 0) {
#pragma unroll
        for (int j = 0; j < 4; j++) {
            const int rl = warpM * 32 + (j >> 1) * 16 + g + (j & 1) * 8;
            part[rl * 4 + warpN] = zp[j];
        }
    }
    __syncthreads();
    if (tid < 128) {
        float s = part[tid * 4] + part[tid * 4 + 1]
                + part[tid * 4 + 2] + part[tid * 4 + 3];
        g_zsq[row0 + tid] = s;
        g_zn[row0 + tid]  = fmaxf(sqrtf(s), COS_EPS_);
    }
}

// ---------------------------------------------------------------------------
// K3 (tf32 mma, measured 24.4us): out = z @ ssfn; dist/sim; log-softmaxes.
// dynsmem u32: Bs 10240 | As 2*4096  (=73728 B)
// ---------------------------------------------------------------------------
__global__ void __launch_bounds__(256) smn_k3_tc(float* __restrict__ dout)
{
    extern __shared__ uint32_t dynsmem[];
    uint32_t* Bs = dynsmem;            // 5 n8grp * 32 kk * 64
    uint32_t* As = dynsmem + 10240;    // 2 * 8 tiles * 4 kk * 128
    __shared__ float csq_s[NCLASS_], cn_s[NCLASS_];

    const int tid  = threadIdx.x;
    const int lane = tid & 31, warp = tid >> 5;
    const int g = lane >> 2, t = lane & 3;
    const long row0 = (long)blockIdx.x * 128;
    const float* zg = dout + Z_OFF;

    for (int e = tid; e < NSSF_ * NCLASS_; e += 256) {
        int k = e / NCLASS_, n = e - k * NCLASS_;
        float v = dout[SSFN_OFF + e];
        int kk = k >> 3, kp = k & 7, tt = kp & 3, hi2 = kp >> 2;
        int phys = (((n & 7) * 4 + tt) + kk * 2) & 31;
        Bs[((n >> 3) * 32 + kk) * 64 + phys * 2 + hi2] = f2tf(v);
    }
    if (tid < NCLASS_) { csq_s[tid] = g_csq[tid]; cn_s[tid] = g_cn[tid]; }

    const int ar[4] = { (tid) >> 3, (tid + 256) >> 3,
                        (tid + 512) >> 3, (tid + 768) >> 3 };
    const int ac  = (tid & 7) * 4;
    const int kkt = ac >> 3, hit = (ac >> 2) & 1, rot = kkt * 2;
    float4 a_reg[4];

    auto stageA3 = [&](uint32_t* dstbuf) {
#pragma unroll
        for (int i = 0; i < 4; i++) {
            const int r = ar[i];
            uint32_t* d = dstbuf + (((r >> 4) * 4 + kkt) * 128)
                        + ((r >> 3) & 1) + 2 * hit;
            const int l0 = (r & 7) * 4;
            d[(((l0 + 0) + rot) & 31) * 4] = f2tf(a_reg[i].x);
            d[(((l0 + 1) + rot) & 31) * 4] = f2tf(a_reg[i].y);
            d[(((l0 + 2) + rot) & 31) * 4] = f2tf(a_reg[i].z);
            d[(((l0 + 3) + rot) & 31) * 4] = f2tf(a_reg[i].w);
        }
    };

    float acc[5][4];
#pragma unroll
    for (int nf = 0; nf < 5; nf++)
#pragma unroll
        for (int v = 0; v < 4; v++) acc[nf][v] = 0.f;

#pragma unroll
    for (int i = 0; i < 4; i++)
        a_reg[i] = *(const float4*)(zg + (row0 + ar[i]) * 256 + ac);
    stageA3(As);
    __syncthreads();

    for (int it = 0; it < 8; it++) {
        const int buf = it & 1;
        if (it < 7) {
            const int ks = (it + 1) * 32;
#pragma unroll
            for (int i = 0; i < 4; i++)
                a_reg[i] = *(const float4*)(zg + (row0 + ar[i]) * 256 + ks + ac);
        }
        const uint32_t* Ab = As + buf * 4096;
#pragma unroll
        for (int kk = 0; kk < 4; kk++) {
            const int kkg = it * 4 + kk;
            const int prA = (lane + kk * 2) & 31;
            const int prB = (lane + kkg * 2) & 31;
            uint4 av = *(const uint4*)&Ab[(warp * 4 + kk) * 128 + prA * 4];
#pragma unroll
            for (int nf = 0; nf < 5; nf++) {
                uint2 bv = *(const uint2*)&Bs[(nf * 32 + kkg) * 64 + prB * 2];
                mma8(acc[nf], reinterpret_cast<const uint32_t*>(&av),
                     reinterpret_cast<const uint32_t*>(&bv));
            }
        }
        if (it < 7) stageA3(As + (buf ^ 1) * 4096);
        __syncthreads();
    }

#pragma unroll
    for (int rs = 0; rs < 2; rs++) {
        const long row = row0 + warp * 16 + g + rs * 8;
        const float zsq = g_zsq[row];
        const float zn  = g_zn[row];
        float dv[5][2], sv[5][2], av[5][2];
        float md = -1e30f, ms = -1e30f;
#pragma unroll
        for (int nf = 0; nf < 5; nf++) {
#pragma unroll
            for (int u = 0; u < 2; u++) {
                const int col = nf * 8 + t * 2 + u;
                float a = acc[nf][rs * 2 + u];
                av[nf][u] = a;
                float d = -sqrtf(fmaxf(zsq + csq_s[col] - 2.f * a, 0.f));
                float s = a / (zn * cn_s[col]);
                dv[nf][u] = d; sv[nf][u] = s;
                md = fmaxf(md, d); ms = fmaxf(ms, s);
            }
        }
        md = fmaxf(md, __shfl_xor_sync(0xffffffffu, md, 1));
        md = fmaxf(md, __shfl_xor_sync(0xffffffffu, md, 2));
        ms = fmaxf(ms, __shfl_xor_sync(0xffffffffu, ms, 1));
        ms = fmaxf(ms, __shfl_xor_sync(0xffffffffu, ms, 2));
        float ed = 0.f, es = 0.f;
#pragma unroll
        for (int nf = 0; nf < 5; nf++)
#pragma unroll
            for (int u = 0; u < 2; u++) {
                ed += expf(dv[nf][u] - md);
                es += expf(sv[nf][u] - ms);
            }
        ed += __shfl_xor_sync(0xffffffffu, ed, 1);
        ed += __shfl_xor_sync(0xffffffffu, ed, 2);
        es += __shfl_xor_sync(0xffffffffu, es, 1);
        es += __shfl_xor_sync(0xffffffffu, es, 2);
        const float lse_d = md + logf(ed);
        const float lse_s = ms + logf(es);
#pragma unroll
        for (int nf = 0; nf < 5; nf++) {
            const int col = nf * 8 + t * 2;
            *(float2*)&dout[OUT_OFF + row * NCLASS_ + col] =
                make_float2(av[nf][0], av[nf][1]);
            *(float2*)&dout[LOSS_OFF + row * NCLASS_ + col] = make_float2(
                0.5f * ((dv[nf][0] - lse_d) + (sv[nf][0] - lse_s)),
                0.5f * ((dv[nf][1] - lse_d) + (sv[nf][1] - lse_s)));
        }
    }
}

// ---------------------------------------------------------------------------
extern "C" void kernel_launch(void* const* d_in, const int* in_sizes, int n_in,
                              void* d_out, int out_size)
{
    const float* x      = (const float*)d_in[0];
    const float* W_pre  = (const float*)d_in[1];
    const float* b_pre  = (const float*)d_in[2];
    const float* att    = (const float*)d_in[3];
    const float* W_post = (const float*)d_in[4];
    const float* b_post = (const float*)d_in[5];
    const float* ssf    = (const float*)d_in[6];
    const float* sigma  = (const float*)d_in[7];
    float* dout = (float*)d_out;

    const int K1_SMEM = (768 + 2 * 96 * 36 + 2 * 128 * 36) * 4;   // 67584
    const int K2_SMEM = (2 * 128 * 36 + 2 * 256 * 36) * 4;        // 110592
    const int K3_SMEM = (10240 + 2 * 4096) * 4;                   // 73728
    cudaFuncSetAttribute(smn_k1_tc,
                         cudaFuncAttributeMaxDynamicSharedMemorySize, K1_SMEM);
    cudaFuncSetAttribute(smn_k2_tc,
                         cudaFuncAttributeMaxDynamicSharedMemorySize, K2_SMEM);
    cudaFuncSetAttribute(smn_k3_tc,
                         cudaFuncAttributeMaxDynamicSharedMemorySize, K3_SMEM);

    smn_wcvt<<<1536, 256>>>(W_pre, W_post);
    smn_k0_ssf<<<1, 256>>>(ssf, sigma, dout);
    smn_k1_tc<<<dim3(4, NN / 16), 256, K1_SMEM>>>(x, b_pre, att);
    smn_k2_tc<<<NN / 128, 512, K2_SMEM>>>(b_post, dout);
    smn_k3_tc<<<NN / 128, 256, K3_SMEM>>>(dout);
}

// round 9
// speedup vs baseline: 1.1304x; 1.0653x over previous
#include <cuda_runtime.h>
#include <math.h>
#include <stdint.h>

#define NN      32768
#define NHOPS   6
#define NFEAT_  512
#define NSSF_   256
#define NCLASS_ 40
#define NEG_    0.2f
#define COS_EPS_ 1e-6f

// output layout (flattened tuple, element offsets)
#define OUT_OFF   0
#define SSFN_OFF  (NN*NCLASS_)                    // 1310720
#define Z_OFF     (SSFN_OFF + NSSF_*NCLASS_)      // 1320960
#define LOSS_OFF  (Z_OFF + NN*NSSF_)              // 9709568
#define SIGMA_OFF (LOSS_OFF + NN*NCLASS_)         // 11020288

// scratch (static device globals — no runtime allocation)
__device__ float g_z1[(long)NN * 512];
__device__ float g_zsq[NN];
__device__ float g_zn[NN];
__device__ float g_csq[NCLASS_];
__device__ float g_cn[NCLASS_];
__device__ uint32_t g_Wp_tf[512 * 512];   // W_pre pre-converted to tf32
__device__ uint32_t g_Wq_tf[256 * 512];   // W_post pre-converted to tf32

// ---------------------------------------------------------------------------
// helpers
// ---------------------------------------------------------------------------
__device__ __forceinline__ uint32_t f2tf(float x) {
    uint32_t y;
    asm("cvt.rna.tf32.f32 %0, %1;" : "=r"(y) : "f"(x));
    return y;
}
__device__ __forceinline__ void mma8(float c[4], const uint32_t a[4],
                                     const uint32_t b[2]) {
    asm volatile(
        "mma.sync.aligned.m16n8k8.row.col.f32.tf32.tf32.f32 "
        "{%0,%1,%2,%3}, {%4,%5,%6,%7}, {%8,%9}, {%0,%1,%2,%3};\n"
        : "+f"(c[0]), "+f"(c[1]), "+f"(c[2]), "+f"(c[3])
        : "r"(a[0]), "r"(a[1]), "r"(a[2]), "r"(a[3]), "r"(b[0]), "r"(b[1]));
}
__device__ __forceinline__ uint32_t smem_u32p(const void* p) {
    uint32_t a;
    asm("{ .reg .u64 t; cvta.to.shared.u64 t, %1; cvt.u32.u64 %0, t; }"
        : "=r"(a) : "l"(p));
    return a;
}
__device__ __forceinline__ void cp16(uint32_t saddr, const void* g) {
    asm volatile("cp.async.ca.shared.global [%0], [%1], 16;"
                 :: "r"(saddr), "l"(g));
}
#define CP_COMMIT() asm volatile("cp.async.commit_group;")
#define CP_WAIT0()  asm volatile("cp.async.wait_group 0;")

// ---------------------------------------------------------------------------
// Kw: pre-convert weights to tf32 (bit-identical to in-loop cvt.rna)
// ---------------------------------------------------------------------------
__global__ void __launch_bounds__(256) smn_wcvt(
    const float* __restrict__ Wp, const float* __restrict__ Wq)
{
    int i = blockIdx.x * 256 + threadIdx.x;
    if (i < 512 * 512) {
        g_Wp_tf[i] = f2tf(Wp[i]);
    } else {
        int j = i - 512 * 512;
        if (j < 256 * 512) g_Wq_tf[j] = f2tf(Wq[j]);
    }
}

// ---------------------------------------------------------------------------
// K0: exact sparsify threshold (5121-st smallest of |ssf|), ssf_norm,
// per-class column norms, sigma copy. One block.
// ---------------------------------------------------------------------------
__global__ void __launch_bounds__(256) smn_k0_ssf(
    const float* __restrict__ ssf, const float* __restrict__ sigma,
    float* __restrict__ dout)
{
    __shared__ float fbuf[NSSF_ * NCLASS_];
    __shared__ int   cnt_s[256];
    unsigned* keys = reinterpret_cast<unsigned*>(fbuf);
    const int tid = threadIdx.x;

    for (int i = tid; i < NSSF_ * NCLASS_; i += 256)
        keys[i] = __float_as_uint(fabsf(ssf[i]));
    __syncthreads();

    unsigned lo = 0u, hi = 0x7f800000u;
    while (lo < hi) {
        unsigned mid = (lo + hi) >> 1;
        int c = 0;
        for (int i = tid; i < NSSF_ * NCLASS_; i += 256) c += (keys[i] <= mid);
        cnt_s[tid] = c;
        __syncthreads();
        for (int s = 128; s > 0; s >>= 1) {
            if (tid < s) cnt_s[tid] += cnt_s[tid + s];
            __syncthreads();
        }
        int total = cnt_s[0];
        __syncthreads();
        if (total >= 5121) hi = mid; else lo = mid + 1;
    }
    const float thr = __uint_as_float(lo);

    float row[NCLASS_];
    float rs = 0.f;
    const float* srow = ssf + tid * NCLASS_;
#pragma unroll
    for (int j = 0; j < NCLASS_; j++) {
        float v = srow[j];
        v = (fabsf(v) >= thr) ? v : 0.f;
        row[j] = v;
        rs += fabsf(v);
    }
    const float inv = 1.f / fmaxf(rs, 1e-12f);
#pragma unroll
    for (int j = 0; j < NCLASS_; j++) {
        float v = row[j] * inv;
        dout[SSFN_OFF + tid * NCLASS_ + j] = v;
        fbuf[tid * NCLASS_ + j] = v;
    }
    __syncthreads();

    if (tid < NCLASS_) {
        float c2 = 0.f;
        for (int i = 0; i < NSSF_; i++) {
            float v = fbuf[i * NCLASS_ + tid];
            c2 += v * v;
        }
        g_csq[tid] = c2;
        g_cn[tid]  = fmaxf(sqrtf(c2), COS_EPS_);
    }
    if (tid < 2) dout[SIGMA_OFF + tid] = sigma[tid];
}

// ---------------------------------------------------------------------------
// K1 (tf32 mma, per-warp kk rotation, forced 2 blocks/SM):
// h = lrelu(x @ W_pre^T + b) -> hop softmax. Block 96x128, warp tile 48x32.
// Dynamic smem: atts[768] | As[2][96][36] | Bs[2][128][36] = 67584 B.
// ---------------------------------------------------------------------------
__global__ void __launch_bounds__(256, 2) smn_k1_tc(
    const float* __restrict__ x,
    const float* __restrict__ bp, const float* __restrict__ att)
{
    extern __shared__ uint32_t dynsmem[];
    float*    atts = (float*)dynsmem;         // 768
    uint32_t* As   = dynsmem + 768;           // 2 * 96*36
    uint32_t* Bs   = As + 2 * 96 * 36;        // 2 * 128*36

    const int tid  = threadIdx.x;
    const int lane = tid & 31, warp = tid >> 5;
    const int warpM = warp >> 2, warpN = warp & 3;
    const int g = lane >> 2, t = lane & 3;
    const int node0 = blockIdx.y * 16;
    const int col0  = blockIdx.x * 128;
    const long row0 = (long)node0 * NHOPS;

    for (int i = tid; i < 768; i += 256)
        atts[i] = att[2 * blockIdx.x * 384 + i];

    const int ar[3] = { (tid + 0)   >> 3, (tid + 256) >> 3, (tid + 512) >> 3 };
    const int bn[4] = { (tid + 0)   >> 3, (tid + 256) >> 3,
                        (tid + 512) >> 3, (tid + 768) >> 3 };
    const int ac    = (tid & 7) * 4;
    float4 a_reg[3];

    // smem byte-addresses for this thread's 4 B slots (buffer 0)
    uint32_t bsa[4];
#pragma unroll
    for (int i = 0; i < 4; i++)
        bsa[i] = smem_u32p(&Bs[bn[i] * 36 + ac]);
    const uint32_t bufB_bytes = 4608 * 4;
    const uint32_t* wsrc[4];
#pragma unroll
    for (int i = 0; i < 4; i++)
        wsrc[i] = g_Wp_tf + (long)(col0 + bn[i]) * 512 + ac;

    float acc[3][4][4];
#pragma unroll
    for (int mf = 0; mf < 3; mf++)
#pragma unroll
        for (int nf = 0; nf < 4; nf++)
#pragma unroll
            for (int v = 0; v < 4; v++) acc[mf][nf][v] = 0.f;

    // prologue: B chunk0 via cp.async; A chunk0 via regs + cvt
#pragma unroll
    for (int i = 0; i < 4; i++) cp16(bsa[i], wsrc[i]);
    CP_COMMIT();
#pragma unroll
    for (int i = 0; i < 3; i++)
        a_reg[i] = *(const float4*)(x + (row0 + ar[i]) * NFEAT_ + ac);
#pragma unroll
    for (int i = 0; i < 3; i++) {
        uint32_t* d = As + ar[i] * 36 + ac;
        *(uint4*)d = make_uint4(f2tf(a_reg[i].x), f2tf(a_reg[i].y),
                                f2tf(a_reg[i].z), f2tf(a_reg[i].w));
    }
    CP_WAIT0();
    __syncthreads();

    for (int it = 0; it < 16; it++) {
        const int buf = it & 1;
        if (it < 15) {
            const int ks = (it + 1) * 32;
#pragma unroll
            for (int i = 0; i < 4; i++)
                cp16(bsa[i] + (buf ^ 1) * bufB_bytes, wsrc[i] + ks);
            CP_COMMIT();
#pragma unroll
            for (int i = 0; i < 3; i++)
                a_reg[i] = *(const float4*)(x + (row0 + ar[i]) * NFEAT_ + ks + ac);
        }
        const uint32_t* Ab = As + buf * 3456;
        const uint32_t* Bb = Bs + buf * 4608;
        // per-warp rotated kk order: deskew LDS/HMMA phases across warps
#pragma unroll
        for (int ki = 0; ki < 4; ki++) {
            const int kk = (ki + warp) & 3;
            const int k8 = kk * 8;
            uint32_t af[3][4], bf[4][2];
#pragma unroll
            for (int mf = 0; mf < 3; mf++) {
                const int rb = warpM * 48 + mf * 16;
                af[mf][0] = Ab[(rb + g)     * 36 + k8 + t];
                af[mf][1] = Ab[(rb + g + 8) * 36 + k8 + t];
                af[mf][2] = Ab[(rb + g)     * 36 + k8 + t + 4];
                af[mf][3] = Ab[(rb + g + 8) * 36 + k8 + t + 4];
            }
#pragma unroll
            for (int nf = 0; nf < 4; nf++) {
                const int nb = warpN * 32 + nf * 8;
                bf[nf][0] = Bb[(nb + g) * 36 + k8 + t];
                bf[nf][1] = Bb[(nb + g) * 36 + k8 + t + 4];
            }
#pragma unroll
            for (int mf = 0; mf < 3; mf++)
#pragma unroll
                for (int nf = 0; nf < 4; nf++)
                    mma8(acc[mf][nf], af[mf], bf[nf]);
        }
        if (it < 15) {
            uint32_t* An = As + (buf ^ 1) * 3456;
#pragma unroll
            for (int i = 0; i < 3; i++) {
                uint32_t* d = An + ar[i] * 36 + ac;
                *(uint4*)d = make_uint4(f2tf(a_reg[i].x), f2tf(a_reg[i].y),
                                        f2tf(a_reg[i].z), f2tf(a_reg[i].w));
            }
            CP_WAIT0();
        }
        __syncthreads();
    }

    // epilogue: two 64-col halves through smem (Cs [96][68] reuses As region)
    float* Cs = (float*)As;
#pragma unroll
    for (int half = 0; half < 2; half++) {
        if ((warpN >> 1) == half) {
#pragma unroll
            for (int mf = 0; mf < 3; mf++)
#pragma unroll
                for (int nf = 0; nf < 4; nf++) {
                    const int r  = warpM * 48 + mf * 16 + g;
                    const int cc = (warpN & 1) * 32 + nf * 8 + t * 2;
                    Cs[r * 68 + cc]           = acc[mf][nf][0];
                    Cs[r * 68 + cc + 1]       = acc[mf][nf][1];
                    Cs[(r + 8) * 68 + cc]     = acc[mf][nf][2];
                    Cs[(r + 8) * 68 + cc + 1] = acc[mf][nf][3];
                }
        }
        __syncthreads();
        {
            const int ty = tid >> 4, tx = tid & 15;
            const int node = node0 + ty;
            const int cg = half * 64 + tx * 4;
            float4 b4 = *(const float4*)(bp + col0 + cg);
            float bv[4] = {b4.x, b4.y, b4.z, b4.w};
            float zr[4];
#pragma unroll
            for (int c = 0; c < 4; c++) {
                float h[NHOPS], am[NHOPS], s[NHOPS];
#pragma unroll
                for (int r = 0; r < NHOPS; r++) {
                    float v = Cs[(ty * 6 + r) * 68 + tx * 4 + c] + bv[c];
                    v = v > 0.f ? v : NEG_ * v;
                    h[r]  = v;
                    am[r] = v * atts[half * 384 + r * 64 + tx * 4 + c];
                }
                float m = -1e30f;
#pragma unroll
                for (int r = 0; r < NHOPS; r++) {
                    float u = am[0] + am[r];
                    u = u > 0.f ? u : NEG_ * u;
                    s[r] = u;
                    m = fmaxf(m, u);
                }
                float den = 0.f, num = 0.f;
#pragma unroll
                for (int r = 0; r < NHOPS; r++) {
                    float w = expf(s[r] - m);
                    den += w;
                    num += h[r] * w;
                }
                zr[c] = num / den;
            }
            *(float4*)&g_z1[(long)node * 512 + col0 + cg] =
                make_float4(zr[0], zr[1], zr[2], zr[3]);
        }
        __syncthreads();
    }
}

// ---------------------------------------------------------------------------
// K2 (tf32 mma, per-warp kk rotation): z = lrelu(z1 @ W_post^T + b),
// plus per-row sum-of-squares + norm. Block 128x256, 512 threads,
// warp tile 32x64. Dynamic smem: As[2][128][36] | Bs[2][256][36] = 110592 B.
// ---------------------------------------------------------------------------
__global__ void __launch_bounds__(512) smn_k2_tc(
    const float* __restrict__ bq, float* __restrict__ dout)
{
    extern __shared__ uint32_t dynsmem[];
    uint32_t* As = dynsmem;                   // 2 * 128*36
    uint32_t* Bs = As + 2 * 128 * 36;         // 2 * 256*36
    __shared__ float bias_s[256];

    const int tid  = threadIdx.x;
    const int lane = tid & 31, warp = tid >> 5;
    const int warpM = warp >> 2, warpN = warp & 3;
    const int g = lane >> 2, t = lane & 3;
    const long row0 = (long)blockIdx.x * 128;

    if (tid < 256) bias_s[tid] = bq[tid];

    const int ar[2] = { (tid + 0) >> 3, (tid + 512) >> 3 };
    const int bn[4] = { (tid + 0) >> 3,    (tid + 512) >> 3,
                        (tid + 1024) >> 3, (tid + 1536) >> 3 };
    const int ac    = (tid & 7) * 4;
    float4 a_reg[2];

    uint32_t bsa[4];
#pragma unroll
    for (int i = 0; i < 4; i++)
        bsa[i] = smem_u32p(&Bs[bn[i] * 36 + ac]);
    const uint32_t bufB_bytes = 9216 * 4;
    const uint32_t* wsrc[4];
#pragma unroll
    for (int i = 0; i < 4; i++)
        wsrc[i] = g_Wq_tf + (long)bn[i] * 512 + ac;

    float acc[2][8][4];
#pragma unroll
    for (int mf = 0; mf < 2; mf++)
#pragma unroll
        for (int nf = 0; nf < 8; nf++)
#pragma unroll
            for (int v = 0; v < 4; v++) acc[mf][nf][v] = 0.f;

#pragma unroll
    for (int i = 0; i < 4; i++) cp16(bsa[i], wsrc[i]);
    CP_COMMIT();
#pragma unroll
    for (int i = 0; i < 2; i++)
        a_reg[i] = *(const float4*)(g_z1 + (row0 + ar[i]) * 512 + ac);
#pragma unroll
    for (int i = 0; i < 2; i++) {
        uint32_t* d = As + ar[i] * 36 + ac;
        *(uint4*)d = make_uint4(f2tf(a_reg[i].x), f2tf(a_reg[i].y),
                                f2tf(a_reg[i].z), f2tf(a_reg[i].w));
    }
    CP_WAIT0();
    __syncthreads();

    for (int it = 0; it < 16; it++) {
        const int buf = it & 1;
        if (it < 15) {
            const int ks = (it + 1) * 32;
#pragma unroll
            for (int i = 0; i < 4; i++)
                cp16(bsa[i] + (buf ^ 1) * bufB_bytes, wsrc[i] + ks);
            CP_COMMIT();
#pragma unroll
            for (int i = 0; i < 2; i++)
                a_reg[i] = *(const float4*)(g_z1 + (row0 + ar[i]) * 512 + ks + ac);
        }
        const uint32_t* Ab = As + buf * 4608;
        const uint32_t* Bb = Bs + buf * 9216;
#pragma unroll
        for (int ki = 0; ki < 4; ki++) {
            const int kk = (ki + warp) & 3;
            const int k8 = kk * 8;
            uint32_t af[2][4], bf[8][2];
#pragma unroll
            for (int mf = 0; mf < 2; mf++) {
                const int rb = warpM * 32 + mf * 16;
                af[mf][0] = Ab[(rb + g)     * 36 + k8 + t];
                af[mf][1] = Ab[(rb + g + 8) * 36 + k8 + t];
                af[mf][2] = Ab[(rb + g)     * 36 + k8 + t + 4];
                af[mf][3] = Ab[(rb + g + 8) * 36 + k8 + t + 4];
            }
#pragma unroll
            for (int nf = 0; nf < 8; nf++) {
                const int nb = warpN * 64 + nf * 8;
                bf[nf][0] = Bb[(nb + g) * 36 + k8 + t];
                bf[nf][1] = Bb[(nb + g) * 36 + k8 + t + 4];
            }
#pragma unroll
            for (int mf = 0; mf < 2; mf++)
#pragma unroll
                for (int nf = 0; nf < 8; nf++)
                    mma8(acc[mf][nf], af[mf], bf[nf]);
        }
        if (it < 15) {
            uint32_t* An = As + (buf ^ 1) * 4608;
#pragma unroll
            for (int i = 0; i < 2; i++) {
                uint32_t* d = An + ar[i] * 36 + ac;
                *(uint4*)d = make_uint4(f2tf(a_reg[i].x), f2tf(a_reg[i].y),
                                        f2tf(a_reg[i].z), f2tf(a_reg[i].w));
            }
            CP_WAIT0();
        }
        __syncthreads();
    }

    // epilogue: bias + lrelu + store z + per-row sum of squares
    float* part = (float*)As;     // [128][4]
    float zp[4] = {0.f, 0.f, 0.f, 0.f};
#pragma unroll
    for (int mf = 0; mf < 2; mf++) {
#pragma unroll
        for (int nf = 0; nf < 8; nf++) {
            const int rl  = warpM * 32 + mf * 16 + g;
            const int col = warpN * 64 + nf * 8 + t * 2;
            float v0 = acc[mf][nf][0] + bias_s[col];
            float v1 = acc[mf][nf][1] + bias_s[col + 1];
            float v2 = acc[mf][nf][2] + bias_s[col];
            float v3 = acc[mf][nf][3] + bias_s[col + 1];
            v0 = v0 > 0.f ? v0 : NEG_ * v0;
            v1 = v1 > 0.f ? v1 : NEG_ * v1;
            v2 = v2 > 0.f ? v2 : NEG_ * v2;
            v3 = v3 > 0.f ? v3 : NEG_ * v3;
            *(float2*)&dout[Z_OFF + (row0 + rl) * 256 + col] =
                make_float2(v0, v1);
            *(float2*)&dout[Z_OFF + (row0 + rl + 8) * 256 + col] =
                make_float2(v2, v3);
            zp[mf * 2]     += v0 * v0 + v1 * v1;
            zp[mf * 2 + 1] += v2 * v2 + v3 * v3;
        }
    }
#pragma unroll
    for (int j = 0; j < 4; j++) {
        zp[j] += __shfl_xor_sync(0xffffffffu, zp[j], 1);
        zp[j] += __shfl_xor_sync(0xffffffffu, zp[j], 2);
    }
    __syncthreads();
    if (t == 0) {
#pragma unroll
        for (int j = 0; j < 4; j++) {
            const int rl = warpM * 32 + (j >> 1) * 16 + g + (j & 1) * 8;
            part[rl * 4 + warpN] = zp[j];
        }
    }
    __syncthreads();
    if (tid < 128) {
        float s = part[tid * 4] + part[tid * 4 + 1]
                + part[tid * 4 + 2] + part[tid * 4 + 3];
        g_zsq[row0 + tid] = s;
        g_zn[row0 + tid]  = fmaxf(sqrtf(s), COS_EPS_);
    }
}

// ---------------------------------------------------------------------------
// K3 (tf32 mma, measured 24.4us): out = z @ ssfn; dist/sim; log-softmaxes.
// dynsmem u32: Bs 10240 | As 2*4096  (=73728 B)
// ---------------------------------------------------------------------------
__global__ void __launch_bounds__(256) smn_k3_tc(float* __restrict__ dout)
{
    extern __shared__ uint32_t dynsmem[];
    uint32_t* Bs = dynsmem;            // 5 n8grp * 32 kk * 64
    uint32_t* As = dynsmem + 10240;    // 2 * 8 tiles * 4 kk * 128
    __shared__ float csq_s[NCLASS_], cn_s[NCLASS_];

    const int tid  = threadIdx.x;
    const int lane = tid & 31, warp = tid >> 5;
    const int g = lane >> 2, t = lane & 3;
    const long row0 = (long)blockIdx.x * 128;
    const float* zg = dout + Z_OFF;

    for (int e = tid; e < NSSF_ * NCLASS_; e += 256) {
        int k = e / NCLASS_, n = e - k * NCLASS_;
        float v = dout[SSFN_OFF + e];
        int kk = k >> 3, kp = k & 7, tt = kp & 3, hi2 = kp >> 2;
        int phys = (((n & 7) * 4 + tt) + kk * 2) & 31;
        Bs[((n >> 3) * 32 + kk) * 64 + phys * 2 + hi2] = f2tf(v);
    }
    if (tid < NCLASS_) { csq_s[tid] = g_csq[tid]; cn_s[tid] = g_cn[tid]; }

    const int ar[4] = { (tid) >> 3, (tid + 256) >> 3,
                        (tid + 512) >> 3, (tid + 768) >> 3 };
    const int ac  = (tid & 7) * 4;
    const int kkt = ac >> 3, hit = (ac >> 2) & 1, rot = kkt * 2;
    float4 a_reg[4];

    auto stageA3 = [&](uint32_t* dstbuf) {
#pragma unroll
        for (int i = 0; i < 4; i++) {
            const int r = ar[i];
            uint32_t* d = dstbuf + (((r >> 4) * 4 + kkt) * 128)
                        + ((r >> 3) & 1) + 2 * hit;
            const int l0 = (r & 7) * 4;
            d[(((l0 + 0) + rot) & 31) * 4] = f2tf(a_reg[i].x);
            d[(((l0 + 1) + rot) & 31) * 4] = f2tf(a_reg[i].y);
            d[(((l0 + 2) + rot) & 31) * 4] = f2tf(a_reg[i].z);
            d[(((l0 + 3) + rot) & 31) * 4] = f2tf(a_reg[i].w);
        }
    };

    float acc[5][4];
#pragma unroll
    for (int nf = 0; nf < 5; nf++)
#pragma unroll
        for (int v = 0; v < 4; v++) acc[nf][v] = 0.f;

#pragma unroll
    for (int i = 0; i < 4; i++)
        a_reg[i] = *(const float4*)(zg + (row0 + ar[i]) * 256 + ac);
    stageA3(As);
    __syncthreads();

    for (int it = 0; it < 8; it++) {
        const int buf = it & 1;
        if (it < 7) {
            const int ks = (it + 1) * 32;
#pragma unroll
            for (int i = 0; i < 4; i++)
                a_reg[i] = *(const float4*)(zg + (row0 + ar[i]) * 256 + ks + ac);
        }
        const uint32_t* Ab = As + buf * 4096;
#pragma unroll
        for (int kk = 0; kk < 4; kk++) {
            const int kkg = it * 4 + kk;
            const int prA = (lane + kk * 2) & 31;
            const int prB = (lane + kkg * 2) & 31;
            uint4 av = *(const uint4*)&Ab[(warp * 4 + kk) * 128 + prA * 4];
#pragma unroll
            for (int nf = 0; nf < 5; nf++) {
                uint2 bv = *(const uint2*)&Bs[(nf * 32 + kkg) * 64 + prB * 2];
                mma8(acc[nf], reinterpret_cast<const uint32_t*>(&av),
                     reinterpret_cast<const uint32_t*>(&bv));
            }
        }
        if (it < 7) stageA3(As + (buf ^ 1) * 4096);
        __syncthreads();
    }

#pragma unroll
    for (int rs = 0; rs < 2; rs++) {
        const long row = row0 + warp * 16 + g + rs * 8;
        const float zsq = g_zsq[row];
        const float zn  = g_zn[row];
        float dv[5][2], sv[5][2], av[5][2];
        float md = -1e30f, ms = -1e30f;
#pragma unroll
        for (int nf = 0; nf < 5; nf++) {
#pragma unroll
            for (int u = 0; u < 2; u++) {
                const int col = nf * 8 + t * 2 + u;
                float a = acc[nf][rs * 2 + u];
                av[nf][u] = a;
                float d = -sqrtf(fmaxf(zsq + csq_s[col] - 2.f * a, 0.f));
                float s = a / (zn * cn_s[col]);
                dv[nf][u] = d; sv[nf][u] = s;
                md = fmaxf(md, d); ms = fmaxf(ms, s);
            }
        }
        md = fmaxf(md, __shfl_xor_sync(0xffffffffu, md, 1));
        md = fmaxf(md, __shfl_xor_sync(0xffffffffu, md, 2));
        ms = fmaxf(ms, __shfl_xor_sync(0xffffffffu, ms, 1));
        ms = fmaxf(ms, __shfl_xor_sync(0xffffffffu, ms, 2));
        float ed = 0.f, es = 0.f;
#pragma unroll
        for (int nf = 0; nf < 5; nf++)
#pragma unroll
            for (int u = 0; u < 2; u++) {
                ed += expf(dv[nf][u] - md);
                es += expf(sv[nf][u] - ms);
            }
        ed += __shfl_xor_sync(0xffffffffu, ed, 1);
        ed += __shfl_xor_sync(0xffffffffu, ed, 2);
        es += __shfl_xor_sync(0xffffffffu, es, 1);
        es += __shfl_xor_sync(0xffffffffu, es, 2);
        const float lse_d = md + logf(ed);
        const float lse_s = ms + logf(es);
#pragma unroll
        for (int nf = 0; nf < 5; nf++) {
            const int col = nf * 8 + t * 2;
            *(float2*)&dout[OUT_OFF + row * NCLASS_ + col] =
                make_float2(av[nf][0], av[nf][1]);
            *(float2*)&dout[LOSS_OFF + row * NCLASS_ + col] = make_float2(
                0.5f * ((dv[nf][0] - lse_d) + (sv[nf][0] - lse_s)),
                0.5f * ((dv[nf][1] - lse_d) + (sv[nf][1] - lse_s)));
        }
    }
}

// ---------------------------------------------------------------------------
extern "C" void kernel_launch(void* const* d_in, const int* in_sizes, int n_in,
                              void* d_out, int out_size)
{
    const float* x      = (const float*)d_in[0];
    const float* W_pre  = (const float*)d_in[1];
    const float* b_pre  = (const float*)d_in[2];
    const float* att    = (const float*)d_in[3];
    const float* W_post = (const float*)d_in[4];
    const float* b_post = (const float*)d_in[5];
    const float* ssf    = (const float*)d_in[6];
    const float* sigma  = (const float*)d_in[7];
    float* dout = (float*)d_out;

    const int K1_SMEM = (768 + 2 * 96 * 36 + 2 * 128 * 36) * 4;   // 67584
    const int K2_SMEM = (2 * 128 * 36 + 2 * 256 * 36) * 4;        // 110592
    const int K3_SMEM = (10240 + 2 * 4096) * 4;                   // 73728
    cudaFuncSetAttribute(smn_k1_tc,
                         cudaFuncAttributeMaxDynamicSharedMemorySize, K1_SMEM);
    cudaFuncSetAttribute(smn_k2_tc,
                         cudaFuncAttributeMaxDynamicSharedMemorySize, K2_SMEM);
    cudaFuncSetAttribute(smn_k3_tc,
                         cudaFuncAttributeMaxDynamicSharedMemorySize, K3_SMEM);

    smn_wcvt<<<1536, 256>>>(W_pre, W_post);
    smn_k0_ssf<<<1, 256>>>(ssf, sigma, dout);
    smn_k1_tc<<<dim3(4, NN / 16), 256, K1_SMEM>>>(x, b_pre, att);
    smn_k2_tc<<<NN / 128, 512, K2_SMEM>>>(b_post, dout);
    smn_k3_tc<<<NN / 128, 256, K3_SMEM>>>(dout);
}